// round 8
// baseline (speedup 1.0000x reference)
#include <cuda_runtime.h>

#define NN 50000
#define EE 800000
#define FF 128
#define LL 3
#define GG 256
#define TT 10

#define BRF 128          // rows per fused block
#define APITCH 36
#define WPITCH 132

// ---- scratch (device globals; no allocation allowed) ----
__device__ float g_f1[NN * FF];
__device__ float g_f2[NN * FF];
__device__ float g_f3[NN * FF];
__device__ float g_WlT[LL * FF * FF];
__device__ float g_WrT[LL * FF * FF];
__device__ float g_W1T[LL * FF * FF];   // [384][128]
__device__ float g_pool[GG * LL * FF];
__device__ float g_z[GG * FF];
__device__ int   g_start[GG + 1];
__device__ int   g_src[EE];
__device__ int   g_dst[EE];
__device__ int   g_csr[EE];
__device__ int   g_rowptr[NN + 1];
__device__ int   g_indeg[NN];
__device__ int   g_cursor[NN];
__device__ int   g_idx64;

// ---- weight pre-transpose: Wl/Wr [l][o][k] -> [l][k][o]; W1 [c][j] -> [j][c] ----
__global__ void gs_transpose_kernel(const float* __restrict__ Wl,
                                    const float* __restrict__ Wr,
                                    const float* __restrict__ W1) {
    int idx = blockIdx.x * blockDim.x + threadIdx.x;
    if (idx < LL * FF * FF) {
        int l = idx / (FF * FF), r = idx % (FF * FF);
        int o = r / FF, k = r % FF;
        g_WlT[l * FF * FF + k * FF + o] = Wl[idx];
        g_WrT[l * FF * FF + k * FF + o] = Wr[idx];
        int c = idx / (LL * FF), j = idx % (LL * FF);
        g_W1T[j * FF + c] = W1[idx];
    }
}

// ---- zero in-degree ----
__global__ void gs_zero_idx_kernel() {
    int i = blockIdx.x * blockDim.x + threadIdx.x;
    if (i < NN) g_indeg[i] = 0;
}

// ---- dtype detection: int64 edge_index has all-zero high words ----
__global__ void gs_detect_kernel(const int* __restrict__ ei32) {
    int is64 = 1;
    for (int i = 1; i < 256; i += 2)
        if (ei32[i] != 0) { is64 = 0; break; }
    g_idx64 = is64;
}

// ---- normalize edge_index to int32 + in-degree histogram (fused) ----
__global__ void gs_convert_count_kernel(const void* __restrict__ ei) {
    int e = blockIdx.x * blockDim.x + threadIdx.x;
    if (e >= EE) return;
    int s, d;
    if (g_idx64) {
        const long long* p = (const long long*)ei;
        s = (int)p[e];
        d = (int)p[EE + e];
    } else {
        const int* p = (const int*)ei;
        s = p[e];
        d = p[EE + e];
    }
    g_src[e] = s;
    g_dst[e] = d;
    atomicAdd(&g_indeg[d], 1);
}

// ---- exclusive prefix scan over indeg -> rowptr + cursor (single block) ----
__global__ void gs_scan_kernel() {
    __shared__ int ssum[1024];
    const int t = threadIdx.x;
    const int CH = (NN + 1023) / 1024;   // 49
    const int base = t * CH;
    int s = 0;
    for (int i = 0; i < CH; i++) {
        int idx = base + i;
        if (idx < NN) s += g_indeg[idx];
    }
    ssum[t] = s;
    __syncthreads();
    for (int off = 1; off < 1024; off <<= 1) {
        int v = (t >= off) ? ssum[t - off] : 0;
        __syncthreads();
        ssum[t] += v;
        __syncthreads();
    }
    int running = (t == 0) ? 0 : ssum[t - 1];
    for (int i = 0; i < CH; i++) {
        int idx = base + i;
        if (idx < NN) {
            g_rowptr[idx] = running;
            g_cursor[idx] = running;
            running += g_indeg[idx];
        }
    }
    if (t == 1023) g_rowptr[NN] = running;
}

// ---- fill CSR edge lists (cursor pre-seeded with rowptr) ----
__global__ void gs_fill_kernel() {
    int e = blockIdx.x * blockDim.x + threadIdx.x;
    if (e >= EE) return;
    int pos = atomicAdd(&g_cursor[g_dst[e]], 1);
    g_csr[pos] = g_src[e];
}

// ---- segment bounds via binary search (batch is sorted) ----
__global__ void gs_bounds_kernel(const void* __restrict__ batch) {
    int g = blockIdx.x * blockDim.x + threadIdx.x;
    if (g > GG) return;
    int is64 = g_idx64;
    const long long* b64 = (const long long*)batch;
    const int* b32 = (const int*)batch;
    int lo = 0, hi = NN;
    while (lo < hi) {
        int mid = (lo + hi) >> 1;
        long long v = is64 ? b64[mid] : (long long)b32[mid];
        if (v < (long long)g) lo = mid + 1; else hi = mid;
    }
    g_start[g] = lo;
}

// ---- fused layer: gather-mean (CSR, in-register) + dual GEMM ----
// hout = mean_agg(hin)@WlT + bl + hin@WrT
__global__ void __launch_bounds__(512) gs_fused_kernel(
    const float* __restrict__ hin,
    const float* __restrict__ WlT, const float* __restrict__ blp,
    const float* __restrict__ WrT, float* __restrict__ hout)
{
    extern __shared__ float sm[];
    float* sWl = sm;                         // 128 x WPITCH
    float* sWr = sWl + FF * WPITCH;          // 128 x WPITCH
    float* sA  = sWr + FF * WPITCH;          // BRF x APITCH (k-chunk of agg)
    float* sH  = sA + BRF * APITCH;          // BRF x APITCH (k-chunk of hin)
    const int t = threadIdx.x;
    const int wid = t >> 5, lane = t & 31;
    const int row0 = blockIdx.x * BRF;

    // load both transposed weight matrices into smem (8 float4 per thread)
    for (int i = t; i < FF * FF / 4; i += 512) {
        int k = i >> 5, c4 = i & 31;
        float4 wl = reinterpret_cast<const float4*>(WlT)[i];
        float4 wr = reinterpret_cast<const float4*>(WrT)[i];
        reinterpret_cast<float4*>(sWl + k * WPITCH)[c4] = wl;
        reinterpret_cast<float4*>(sWr + k * WPITCH)[c4] = wr;
    }

    // gather phase: each warp computes 8 full agg rows in registers.
    // lane holds floats [lane*4, lane*4+4) of the 128-float row.
    float4 gRegs[8];
#pragma unroll
    for (int rr = 0; rr < 8; rr++) {
        int gr = row0 + wid * 8 + rr;
        float4 acc = make_float4(0.f, 0.f, 0.f, 0.f);
        if (gr < NN) {
            int s0 = g_rowptr[gr], s1 = g_rowptr[gr + 1];
            int j = s0;
            for (; j + 4 <= s1; j += 4) {
                int a = g_csr[j], b = g_csr[j + 1], c = g_csr[j + 2], d = g_csr[j + 3];
                float4 v0 = reinterpret_cast<const float4*>(hin + (size_t)a * FF)[lane];
                float4 v1 = reinterpret_cast<const float4*>(hin + (size_t)b * FF)[lane];
                float4 v2 = reinterpret_cast<const float4*>(hin + (size_t)c * FF)[lane];
                float4 v3 = reinterpret_cast<const float4*>(hin + (size_t)d * FF)[lane];
                acc.x += (v0.x + v1.x) + (v2.x + v3.x);
                acc.y += (v0.y + v1.y) + (v2.y + v3.y);
                acc.z += (v0.z + v1.z) + (v2.z + v3.z);
                acc.w += (v0.w + v1.w) + (v2.w + v3.w);
            }
            for (; j < s1; j++) {
                int s = g_csr[j];
                float4 v = reinterpret_cast<const float4*>(hin + (size_t)s * FF)[lane];
                acc.x += v.x; acc.y += v.y; acc.z += v.z; acc.w += v.w;
            }
            float iv = (s1 > s0) ? 1.f / (float)(s1 - s0) : 0.f;
            acc.x *= iv; acc.y *= iv; acc.z *= iv; acc.w *= iv;
        }
        gRegs[rr] = acc;
    }

    const int tc = t & 15, tr = t >> 4;        // 16 x 32 thread grid
    const int cA = tc * 4, cB = 64 + tc * 4, r0 = tr * 4;

    float acc[4][8];
#pragma unroll
    for (int i = 0; i < 4; i++)
#pragma unroll
        for (int j = 0; j < 8; j++) acc[i][j] = 0.f;

    for (int kc = 0; kc < FF; kc += 32) {
        __syncthreads();   // previous chunk's compute done (WAR on sA/sH)
        // owning warp deposits its agg slice for this k-chunk
        {
            int l0 = kc >> 2;                  // first active float4-lane
            if (lane >= l0 && lane < l0 + 8) {
#pragma unroll
                for (int rr = 0; rr < 8; rr++) {
                    reinterpret_cast<float4*>(sA + (wid * 8 + rr) * APITCH)[lane - l0] =
                        gRegs[rr];
                }
            }
        }
        // stream hin chunk
        for (int i = t; i < BRF * 8; i += 512) {
            int r = i >> 3, k4 = i & 7;
            int gr = row0 + r; if (gr >= NN) gr = NN - 1;
            reinterpret_cast<float4*>(sH + r * APITCH)[k4] =
                reinterpret_cast<const float4*>(hin + (size_t)gr * FF + kc)[k4];
        }
        __syncthreads();
#pragma unroll
        for (int k = 0; k < 32; k++) {
            const float* wrow_l = sWl + (kc + k) * WPITCH;
            const float* wrow_r = sWr + (kc + k) * WPITCH;
            float4 wl0 = *reinterpret_cast<const float4*>(wrow_l + cA);
            float4 wl1 = *reinterpret_cast<const float4*>(wrow_l + cB);
            float4 wr0 = *reinterpret_cast<const float4*>(wrow_r + cA);
            float4 wr1 = *reinterpret_cast<const float4*>(wrow_r + cB);
#pragma unroll
            for (int i = 0; i < 4; i++) {
                float a = sA[(r0 + i) * APITCH + k];
                float h = sH[(r0 + i) * APITCH + k];
                acc[i][0] += a * wl0.x + h * wr0.x;
                acc[i][1] += a * wl0.y + h * wr0.y;
                acc[i][2] += a * wl0.z + h * wr0.z;
                acc[i][3] += a * wl0.w + h * wr0.w;
                acc[i][4] += a * wl1.x + h * wr1.x;
                acc[i][5] += a * wl1.y + h * wr1.y;
                acc[i][6] += a * wl1.z + h * wr1.z;
                acc[i][7] += a * wl1.w + h * wr1.w;
            }
        }
    }

    float4 b0 = *reinterpret_cast<const float4*>(blp + cA);
    float4 b1v = *reinterpret_cast<const float4*>(blp + cB);
#pragma unroll
    for (int i = 0; i < 4; i++) {
        int gr = row0 + r0 + i;
        if (gr < NN) {
            float4 o0 = make_float4(acc[i][0] + b0.x, acc[i][1] + b0.y,
                                    acc[i][2] + b0.z, acc[i][3] + b0.w);
            float4 o1 = make_float4(acc[i][4] + b1v.x, acc[i][5] + b1v.y,
                                    acc[i][6] + b1v.z, acc[i][7] + b1v.w);
            *reinterpret_cast<float4*>(hout + (size_t)gr * FF + cA) = o0;
            *reinterpret_cast<float4*>(hout + (size_t)gr * FF + cB) = o1;
        }
    }
}

// ---- global max pool over each graph segment; one block per graph ----
__global__ void gs_pool_kernel() {
    int g = blockIdx.x;
    int s = g_start[g], e = g_start[g + 1];
    int t = threadIdx.x;            // 0..383
    int l = t >> 7, c = t & 127;
    const float* f = (l == 0) ? g_f1 : (l == 1) ? g_f2 : g_f3;
    float m = -3.402823466e38f;
    int i = s;
    for (; i + 4 <= e; i += 4) {
        float v0 = f[(size_t)(i + 0) * FF + c];
        float v1 = f[(size_t)(i + 1) * FF + c];
        float v2 = f[(size_t)(i + 2) * FF + c];
        float v3 = f[(size_t)(i + 3) * FF + c];
        m = fmaxf(m, fmaxf(fmaxf(v0, v1), fmaxf(v2, v3)));
    }
    for (; i < e; i++) m = fmaxf(m, f[(size_t)i * FF + c]);
    g_pool[g * (LL * FF) + t] = m;
}

// ---- MLP layer 1: z = relu(pool @ W1^T + b1) ----
__global__ void gs_mlp1_kernel(const float* __restrict__ b1) {
    __shared__ float sp[LL * FF];
    int g = blockIdx.x, t = threadIdx.x;   // 128 threads
    for (int i = t; i < LL * FF; i += FF) sp[i] = g_pool[g * (LL * FF) + i];
    __syncthreads();
    float acc = b1[t];
#pragma unroll 8
    for (int j = 0; j < LL * FF; j++) acc += sp[j] * g_W1T[j * FF + t];
    g_z[g * FF + t] = fmaxf(acc, 0.f);
}

// ---- MLP layer 2: out = z @ W2^T + b2 ----
__global__ void gs_mlp2_kernel(const float* __restrict__ W2,
                               const float* __restrict__ b2,
                               float* __restrict__ out) {
    __shared__ float sz[FF];
    int g = blockIdx.x, t = threadIdx.x;   // 128 threads
    sz[t] = g_z[g * FF + t];
    __syncthreads();
    if (t < TT) {
        float acc = b2[t];
#pragma unroll
        for (int c = 0; c < FF; c++) acc += sz[c] * W2[t * FF + c];
        out[g * TT + t] = acc;
    }
}

extern "C" void kernel_launch(void* const* d_in, const int* in_sizes, int n_in,
                              void* d_out, int out_size) {
    const float* x     = (const float*)d_in[0];
    const void*  ei    = d_in[1];
    const void*  batch = d_in[2];
    const float* Wl    = (const float*)d_in[3];
    const float* bl    = (const float*)d_in[4];
    const float* Wr    = (const float*)d_in[5];
    const float* W1    = (const float*)d_in[6];
    const float* b1    = (const float*)d_in[7];
    const float* W2    = (const float*)d_in[8];
    const float* b2    = (const float*)d_in[9];
    float* out = (float*)d_out;

    size_t smem = (size_t)(FF * WPITCH * 2 + BRF * APITCH * 2) * sizeof(float);
    cudaFuncSetAttribute(gs_fused_kernel,
                         cudaFuncAttributeMaxDynamicSharedMemorySize, (int)smem);

    gs_transpose_kernel<<<(LL * FF * FF + 255) / 256, 256>>>(Wl, Wr, W1);
    gs_zero_idx_kernel<<<(NN + 255) / 256, 256>>>();
    gs_detect_kernel<<<1, 1>>>((const int*)ei);
    gs_convert_count_kernel<<<(EE + 255) / 256, 256>>>(ei);
    gs_scan_kernel<<<1, 1024>>>();
    gs_fill_kernel<<<(EE + 255) / 256, 256>>>();
    gs_bounds_kernel<<<1, GG + 1>>>(batch);

    void *p_f1, *p_f2, *p_f3, *p_wlt, *p_wrt;
    cudaGetSymbolAddress(&p_f1, g_f1);
    cudaGetSymbolAddress(&p_f2, g_f2);
    cudaGetSymbolAddress(&p_f3, g_f3);
    cudaGetSymbolAddress(&p_wlt, g_WlT);
    cudaGetSymbolAddress(&p_wrt, g_WrT);
    float* fbuf_sel[3] = {(float*)p_f1, (float*)p_f2, (float*)p_f3};

    const float* hin = x;
    for (int l = 0; l < LL; l++) {
        gs_fused_kernel<<<(NN + BRF - 1) / BRF, 512, smem>>>(
            hin,
            (const float*)p_wlt + (size_t)l * FF * FF, bl + l * FF,
            (const float*)p_wrt + (size_t)l * FF * FF, fbuf_sel[l]);
        hin = fbuf_sel[l];
    }

    gs_pool_kernel<<<GG, LL * FF>>>();
    gs_mlp1_kernel<<<GG, FF>>>(b1);
    gs_mlp2_kernel<<<GG, FF>>>(W2, b2, out);
}

// round 9
// speedup vs baseline: 1.0529x; 1.0529x over previous
#include <cuda_runtime.h>

#define NN 50000
#define EE 800000
#define FF 128
#define LL 3
#define GG 256
#define TT 10

#define BRF 128          // rows per GEMM block
#define APITCH 36
#define WPITCH 132

// ---- scratch (device globals; no allocation allowed) ----
__device__ float g_agg[NN * FF];
__device__ float g_f1[NN * FF];
__device__ float g_f2[NN * FF];
__device__ float g_f3[NN * FF];
__device__ float g_WlT[LL * FF * FF];
__device__ float g_WrT[LL * FF * FF];
__device__ float g_W1T[LL * FF * FF];   // [384][128]
__device__ float g_pool[GG * LL * FF];
__device__ float g_z[GG * FF];
__device__ int   g_start[GG + 1];
__device__ int   g_src[EE];
__device__ int   g_dst[EE];
__device__ int   g_csr[EE];
__device__ int   g_rowptr[NN + 1];
__device__ int   g_indeg[NN];
__device__ int   g_cursor[NN];
__device__ int   g_idx64;

// ---- weight pre-transpose: Wl/Wr [l][o][k] -> [l][k][o]; W1 [c][j] -> [j][c] ----
__global__ void gs_transpose_kernel(const float* __restrict__ Wl,
                                    const float* __restrict__ Wr,
                                    const float* __restrict__ W1) {
    int idx = blockIdx.x * blockDim.x + threadIdx.x;
    if (idx < LL * FF * FF) {
        int l = idx / (FF * FF), r = idx % (FF * FF);
        int o = r / FF, k = r % FF;
        g_WlT[l * FF * FF + k * FF + o] = Wl[idx];
        g_WrT[l * FF * FF + k * FF + o] = Wr[idx];
        int c = idx / (LL * FF), j = idx % (LL * FF);
        g_W1T[j * FF + c] = W1[idx];
    }
}

// ---- zero in-degree ----
__global__ void gs_zero_idx_kernel() {
    int i = blockIdx.x * blockDim.x + threadIdx.x;
    if (i < NN) g_indeg[i] = 0;
}

// ---- dtype detection: int64 edge_index has all-zero high words ----
__global__ void gs_detect_kernel(const int* __restrict__ ei32) {
    int is64 = 1;
    for (int i = 1; i < 256; i += 2)
        if (ei32[i] != 0) { is64 = 0; break; }
    g_idx64 = is64;
}

// ---- normalize edge_index to int32 + in-degree histogram (fused) ----
__global__ void gs_convert_count_kernel(const void* __restrict__ ei) {
    int e = blockIdx.x * blockDim.x + threadIdx.x;
    if (e >= EE) return;
    int s, d;
    if (g_idx64) {
        const long long* p = (const long long*)ei;
        s = (int)p[e];
        d = (int)p[EE + e];
    } else {
        const int* p = (const int*)ei;
        s = p[e];
        d = p[EE + e];
    }
    g_src[e] = s;
    g_dst[e] = d;
    atomicAdd(&g_indeg[d], 1);
}

// ---- exclusive prefix scan over indeg -> rowptr + cursor (single block) ----
__global__ void gs_scan_kernel() {
    __shared__ int ssum[1024];
    const int t = threadIdx.x;
    const int CH = (NN + 1023) / 1024;   // 49
    const int base = t * CH;
    int s = 0;
    for (int i = 0; i < CH; i++) {
        int idx = base + i;
        if (idx < NN) s += g_indeg[idx];
    }
    ssum[t] = s;
    __syncthreads();
    for (int off = 1; off < 1024; off <<= 1) {
        int v = (t >= off) ? ssum[t - off] : 0;
        __syncthreads();
        ssum[t] += v;
        __syncthreads();
    }
    int running = (t == 0) ? 0 : ssum[t - 1];
    for (int i = 0; i < CH; i++) {
        int idx = base + i;
        if (idx < NN) {
            g_rowptr[idx] = running;
            g_cursor[idx] = running;
            running += g_indeg[idx];
        }
    }
    if (t == 1023) g_rowptr[NN] = running;
}

// ---- fill CSR edge lists (cursor pre-seeded with rowptr) ----
__global__ void gs_fill_kernel() {
    int e = blockIdx.x * blockDim.x + threadIdx.x;
    if (e >= EE) return;
    int pos = atomicAdd(&g_cursor[g_dst[e]], 1);
    g_csr[pos] = g_src[e];
}

// ---- segment bounds via binary search (batch is sorted) ----
__global__ void gs_bounds_kernel(const void* __restrict__ batch) {
    int g = blockIdx.x * blockDim.x + threadIdx.x;
    if (g > GG) return;
    int is64 = g_idx64;
    const long long* b64 = (const long long*)batch;
    const int* b32 = (const int*)batch;
    int lo = 0, hi = NN;
    while (lo < hi) {
        int mid = (lo + hi) >> 1;
        long long v = is64 ? b64[mid] : (long long)b32[mid];
        if (v < (long long)g) lo = mid + 1; else hi = mid;
    }
    g_start[g] = lo;
}

// ---- gather-mean aggregation: one warp per dst node, no atomics ----
__global__ void __launch_bounds__(256) gs_gather_kernel(const float* __restrict__ h) {
    int warp = (blockIdx.x * blockDim.x + threadIdx.x) >> 5;
    int lane = threadIdx.x & 31;
    if (warp >= NN) return;
    int s0 = g_rowptr[warp], s1 = g_rowptr[warp + 1];
    float4 acc = make_float4(0.f, 0.f, 0.f, 0.f);
    int j = s0;
    for (; j + 4 <= s1; j += 4) {
        int a = g_csr[j], b = g_csr[j + 1], c = g_csr[j + 2], d = g_csr[j + 3];
        float4 v0 = reinterpret_cast<const float4*>(h + (size_t)a * FF)[lane];
        float4 v1 = reinterpret_cast<const float4*>(h + (size_t)b * FF)[lane];
        float4 v2 = reinterpret_cast<const float4*>(h + (size_t)c * FF)[lane];
        float4 v3 = reinterpret_cast<const float4*>(h + (size_t)d * FF)[lane];
        acc.x += (v0.x + v1.x) + (v2.x + v3.x);
        acc.y += (v0.y + v1.y) + (v2.y + v3.y);
        acc.z += (v0.z + v1.z) + (v2.z + v3.z);
        acc.w += (v0.w + v1.w) + (v2.w + v3.w);
    }
    for (; j < s1; j++) {
        int s = g_csr[j];
        float4 v = reinterpret_cast<const float4*>(h + (size_t)s * FF)[lane];
        acc.x += v.x; acc.y += v.y; acc.z += v.z; acc.w += v.w;
    }
    float iv = (s1 > s0) ? 1.f / (float)(s1 - s0) : 0.f;
    acc.x *= iv; acc.y *= iv; acc.z *= iv; acc.w *= iv;
    reinterpret_cast<float4*>(g_agg + (size_t)warp * FF)[lane] = acc;
}

// ---- fused SAGE layer GEMM (512 thr, 128 rows): hout = agg@WlT + bl + hin@WrT ----
__global__ void __launch_bounds__(512) gs_gemm_kernel(
    const float* __restrict__ hin,
    const float* __restrict__ WlT, const float* __restrict__ blp,
    const float* __restrict__ WrT, float* __restrict__ hout)
{
    extern __shared__ float sm[];
    float* sWl = sm;                         // 128 x WPITCH
    float* sWr = sWl + FF * WPITCH;          // 128 x WPITCH
    float* sA  = sWr + FF * WPITCH;          // BRF x APITCH
    float* sH  = sA + BRF * APITCH;          // BRF x APITCH
    const int t = threadIdx.x;
    const int row0 = blockIdx.x * BRF;

    // load both transposed weight matrices into smem
    for (int i = t; i < FF * FF / 4; i += 512) {
        int k = i >> 5, c4 = i & 31;
        float4 wl = reinterpret_cast<const float4*>(WlT)[i];
        float4 wr = reinterpret_cast<const float4*>(WrT)[i];
        reinterpret_cast<float4*>(sWl + k * WPITCH)[c4] = wl;
        reinterpret_cast<float4*>(sWr + k * WPITCH)[c4] = wr;
    }

    const int tc = t & 15, tr = t >> 4;      // 16 col-groups x 32 row-groups
    const int cA = tc * 4, cB = 64 + tc * 4, r0 = tr * 4;

    float acc[4][8];
#pragma unroll
    for (int i = 0; i < 4; i++)
#pragma unroll
        for (int j = 0; j < 8; j++) acc[i][j] = 0.f;

    for (int kc = 0; kc < FF; kc += 32) {
        __syncthreads();
        // stream 128x32 chunks of agg and hin into smem
        for (int i = t; i < BRF * 8; i += 512) {
            int r = i >> 3, k4 = i & 7;
            int gr = row0 + r; if (gr >= NN) gr = NN - 1;
            reinterpret_cast<float4*>(sA + r * APITCH)[k4] =
                reinterpret_cast<const float4*>(g_agg + (size_t)gr * FF + kc)[k4];
            reinterpret_cast<float4*>(sH + r * APITCH)[k4] =
                reinterpret_cast<const float4*>(hin + (size_t)gr * FF + kc)[k4];
        }
        __syncthreads();
#pragma unroll
        for (int k = 0; k < 32; k++) {
            const float* wrow_l = sWl + (kc + k) * WPITCH;
            const float* wrow_r = sWr + (kc + k) * WPITCH;
            float4 wl0 = *reinterpret_cast<const float4*>(wrow_l + cA);
            float4 wl1 = *reinterpret_cast<const float4*>(wrow_l + cB);
            float4 wr0 = *reinterpret_cast<const float4*>(wrow_r + cA);
            float4 wr1 = *reinterpret_cast<const float4*>(wrow_r + cB);
#pragma unroll
            for (int i = 0; i < 4; i++) {
                float a = sA[(r0 + i) * APITCH + k];
                float h = sH[(r0 + i) * APITCH + k];
                acc[i][0] += a * wl0.x + h * wr0.x;
                acc[i][1] += a * wl0.y + h * wr0.y;
                acc[i][2] += a * wl0.z + h * wr0.z;
                acc[i][3] += a * wl0.w + h * wr0.w;
                acc[i][4] += a * wl1.x + h * wr1.x;
                acc[i][5] += a * wl1.y + h * wr1.y;
                acc[i][6] += a * wl1.z + h * wr1.z;
                acc[i][7] += a * wl1.w + h * wr1.w;
            }
        }
    }

    float4 b0 = *reinterpret_cast<const float4*>(blp + cA);
    float4 b1v = *reinterpret_cast<const float4*>(blp + cB);
#pragma unroll
    for (int i = 0; i < 4; i++) {
        int gr = row0 + r0 + i;
        if (gr < NN) {
            float4 o0 = make_float4(acc[i][0] + b0.x, acc[i][1] + b0.y,
                                    acc[i][2] + b0.z, acc[i][3] + b0.w);
            float4 o1 = make_float4(acc[i][4] + b1v.x, acc[i][5] + b1v.y,
                                    acc[i][6] + b1v.z, acc[i][7] + b1v.w);
            *reinterpret_cast<float4*>(hout + (size_t)gr * FF + cA) = o0;
            *reinterpret_cast<float4*>(hout + (size_t)gr * FF + cB) = o1;
        }
    }
}

// ---- global max pool over each graph segment; one block per graph ----
__global__ void gs_pool_kernel() {
    int g = blockIdx.x;
    int s = g_start[g], e = g_start[g + 1];
    int t = threadIdx.x;            // 0..383
    int l = t >> 7, c = t & 127;
    const float* f = (l == 0) ? g_f1 : (l == 1) ? g_f2 : g_f3;
    float m = -3.402823466e38f;
    int i = s;
    for (; i + 4 <= e; i += 4) {
        float v0 = f[(size_t)(i + 0) * FF + c];
        float v1 = f[(size_t)(i + 1) * FF + c];
        float v2 = f[(size_t)(i + 2) * FF + c];
        float v3 = f[(size_t)(i + 3) * FF + c];
        m = fmaxf(m, fmaxf(fmaxf(v0, v1), fmaxf(v2, v3)));
    }
    for (; i < e; i++) m = fmaxf(m, f[(size_t)i * FF + c]);
    g_pool[g * (LL * FF) + t] = m;
}

// ---- MLP layer 1: z = relu(pool @ W1^T + b1) ----
__global__ void gs_mlp1_kernel(const float* __restrict__ b1) {
    __shared__ float sp[LL * FF];
    int g = blockIdx.x, t = threadIdx.x;   // 128 threads
    for (int i = t; i < LL * FF; i += FF) sp[i] = g_pool[g * (LL * FF) + i];
    __syncthreads();
    float acc = b1[t];
#pragma unroll 8
    for (int j = 0; j < LL * FF; j++) acc += sp[j] * g_W1T[j * FF + t];
    g_z[g * FF + t] = fmaxf(acc, 0.f);
}

// ---- MLP layer 2: out = z @ W2^T + b2 ----
__global__ void gs_mlp2_kernel(const float* __restrict__ W2,
                               const float* __restrict__ b2,
                               float* __restrict__ out) {
    __shared__ float sz[FF];
    int g = blockIdx.x, t = threadIdx.x;   // 128 threads
    sz[t] = g_z[g * FF + t];
    __syncthreads();
    if (t < TT) {
        float acc = b2[t];
#pragma unroll
        for (int c = 0; c < FF; c++) acc += sz[c] * W2[t * FF + c];
        out[g * TT + t] = acc;
    }
}

extern "C" void kernel_launch(void* const* d_in, const int* in_sizes, int n_in,
                              void* d_out, int out_size) {
    const float* x     = (const float*)d_in[0];
    const void*  ei    = d_in[1];
    const void*  batch = d_in[2];
    const float* Wl    = (const float*)d_in[3];
    const float* bl    = (const float*)d_in[4];
    const float* Wr    = (const float*)d_in[5];
    const float* W1    = (const float*)d_in[6];
    const float* b1    = (const float*)d_in[7];
    const float* W2    = (const float*)d_in[8];
    const float* b2    = (const float*)d_in[9];
    float* out = (float*)d_out;

    size_t smem = (size_t)(FF * WPITCH * 2 + BRF * APITCH * 2) * sizeof(float);
    cudaFuncSetAttribute(gs_gemm_kernel,
                         cudaFuncAttributeMaxDynamicSharedMemorySize, (int)smem);

    gs_transpose_kernel<<<(LL * FF * FF + 255) / 256, 256>>>(Wl, Wr, W1);
    gs_zero_idx_kernel<<<(NN + 255) / 256, 256>>>();
    gs_detect_kernel<<<1, 1>>>((const int*)ei);
    gs_convert_count_kernel<<<(EE + 255) / 256, 256>>>(ei);
    gs_scan_kernel<<<1, 1024>>>();
    gs_fill_kernel<<<(EE + 255) / 256, 256>>>();
    gs_bounds_kernel<<<1, GG + 1>>>(batch);

    void *p_f1, *p_f2, *p_f3, *p_wlt, *p_wrt;
    cudaGetSymbolAddress(&p_f1, g_f1);
    cudaGetSymbolAddress(&p_f2, g_f2);
    cudaGetSymbolAddress(&p_f3, g_f3);
    cudaGetSymbolAddress(&p_wlt, g_WlT);
    cudaGetSymbolAddress(&p_wrt, g_WrT);
    float* fbuf_sel[3] = {(float*)p_f1, (float*)p_f2, (float*)p_f3};

    const float* hin = x;
    for (int l = 0; l < LL; l++) {
        gs_gather_kernel<<<(NN * 32 + 255) / 256, 256>>>(hin);
        gs_gemm_kernel<<<(NN + BRF - 1) / BRF, 512, smem>>>(
            hin,
            (const float*)p_wlt + (size_t)l * FF * FF, bl + l * FF,
            (const float*)p_wrt + (size_t)l * FF * FF, fbuf_sel[l]);
        hin = fbuf_sel[l];
    }

    gs_pool_kernel<<<GG, LL * FF>>>();
    gs_mlp1_kernel<<<GG, FF>>>(b1);
    gs_mlp2_kernel<<<GG, FF>>>(W2, b2, out);
}